// round 8
// baseline (speedup 1.0000x reference)
#include <cuda_runtime.h>
#include <math.h>

#define D_MODEL  1024
#define D_FF     4096
#define N_EXPERTS 8
#define T_TOKENS 8192
#define TOPK     2
#define NPAIRS   (T_TOKENS * TOPK)          // 16384

#define TM  64
#define TN  64
#define TKK 16
#define ROWS_CAP  (NPAIRS + N_EXPERTS * TM) // 16896 (each expert segment padded to TM)
#define MAX_TILES (ROWS_CAP / TM)           // 264

// ---------------- static device scratch (allocation-free) ----------------
__device__ float g_H[(size_t)ROWS_CAP * D_FF];   // intermediate gelu(x@w1^T)
__device__ int   g_sorted_token[ROWS_CAP];       // pair rows grouped by expert, -1 = pad
__device__ float g_sorted_gate[ROWS_CAP];
__device__ int   g_off[N_EXPERTS + 1];           // padded segment offsets
__device__ int   g_count[N_EXPERTS];
__device__ int   g_tile_expert[MAX_TILES];       // expert per 64-row tile, -1 = unused
__device__ int   g_pair_expert[NPAIRS];
__device__ float g_pair_gate[NPAIRS];
__device__ int   g_pair_rank[NPAIRS];

// ---------------- init: zero out, counts, pad markers ----------------
__global__ void k_init(float* __restrict__ out) {
    int stride = gridDim.x * blockDim.x;
    int i0 = blockIdx.x * blockDim.x + threadIdx.x;
    const int n = T_TOKENS * D_MODEL;
    for (int i = i0; i < n; i += stride) out[i] = 0.0f;
    for (int i = i0; i < ROWS_CAP; i += stride) g_sorted_token[i] = -1;
    if (i0 < N_EXPERTS) g_count[i0] = 0;
}

// ---------------- router: one warp per token ----------------
__global__ void k_router(const float* __restrict__ x,
                         const float* __restrict__ rw,
                         const float* __restrict__ rb) {
    int warp = (blockIdx.x * blockDim.x + threadIdx.x) >> 5;
    int lane = threadIdx.x & 31;
    if (warp >= T_TOKENS) return;
    const float* xt = x + (size_t)warp * D_MODEL;

    float lg[N_EXPERTS];
#pragma unroll
    for (int e = 0; e < N_EXPERTS; e++) {
        const float* we = rw + e * D_MODEL;
        float s = 0.0f;
        for (int d = lane; d < D_MODEL; d += 32) s = fmaf(xt[d], we[d], s);
#pragma unroll
        for (int o = 16; o > 0; o >>= 1) s += __shfl_down_sync(0xffffffffu, s, o);
        lg[e] = s;
    }
    if (lane == 0) {
        float m = -1e30f;
#pragma unroll
        for (int e = 0; e < N_EXPERTS; e++) { lg[e] += rb[e]; m = fmaxf(m, lg[e]); }
        float p[N_EXPERTS];
#pragma unroll
        for (int e = 0; e < N_EXPERTS; e++) p[e] = expf(lg[e] - m);
        int i1 = 0;
#pragma unroll
        for (int e = 1; e < N_EXPERTS; e++) if (p[e] > p[i1]) i1 = e;   // ties -> lower idx
        int i2 = (i1 == 0) ? 1 : 0;
#pragma unroll
        for (int e = 0; e < N_EXPERTS; e++) if (e != i1 && p[e] > p[i2]) i2 = e;
        float s2 = p[i1] + p[i2];
        g_pair_expert[warp * 2 + 0] = i1;
        g_pair_expert[warp * 2 + 1] = i2;
        g_pair_gate[warp * 2 + 0] = p[i1] / s2;
        g_pair_gate[warp * 2 + 1] = p[i2] / s2;
        g_pair_rank[warp * 2 + 0] = atomicAdd(&g_count[i1], 1);
        g_pair_rank[warp * 2 + 1] = atomicAdd(&g_count[i2], 1);
    }
}

// ---------------- offsets + tile->expert map (single thread, trivial) ----
__global__ void k_setup() {
    int off = 0;
    for (int e = 0; e < N_EXPERTS; e++) {
        g_off[e] = off;
        off += (g_count[e] + TM - 1) / TM * TM;
    }
    g_off[N_EXPERTS] = off;
    int nt = off / TM;
    for (int i = 0; i < MAX_TILES; i++) {
        int te = -1;
        if (i < nt) {
            int r = i * TM;
            for (int e = 0; e < N_EXPERTS; e++)
                if (r >= g_off[e] && r < g_off[e + 1]) { te = e; break; }
        }
        g_tile_expert[i] = te;
    }
}

// ---------------- scatter pairs into expert-grouped rows ----------------
__global__ void k_scatter() {
    int i = blockIdx.x * blockDim.x + threadIdx.x;
    if (i >= NPAIRS) return;
    int e = g_pair_expert[i];
    int r = g_off[e] + g_pair_rank[i];
    g_sorted_token[r] = i >> 1;
    g_sorted_gate[r]  = g_pair_gate[i];
}

// ---------------- pass 1: H = gelu(X_e @ w1[e]^T + b1[e]) ----------------
__global__ void __launch_bounds__(256) k_ffn1(const float* __restrict__ x,
                                              const float* __restrict__ w1,
                                              const float* __restrict__ b1) {
    int e = g_tile_expert[blockIdx.x];
    if (e < 0) return;
    int r0 = blockIdx.x * TM;
    int f0 = blockIdx.y * TN;

    __shared__ float As[TKK][TM];
    __shared__ float Bs[TKK][TN];
    __shared__ int   tok[TM];

    int tid = threadIdx.x;
    if (tid < TM) tok[tid] = g_sorted_token[r0 + tid];
    __syncthreads();
    if (tok[0] < 0) return;   // fully padded tile (padding is at segment tail)

    float acc[4][4] = {};
    int ty = tid >> 4, tx = tid & 15;
    const float* wb = w1 + ((size_t)e * D_FF + f0) * D_MODEL;

    for (int k0 = 0; k0 < D_MODEL; k0 += TKK) {
#pragma unroll
        for (int i = 0; i < 4; i++) {
            int li = tid + i * 256;
            int row = li >> 4, kk = li & 15;
            int t = tok[row];
            As[kk][row] = (t >= 0) ? x[(size_t)t * D_MODEL + k0 + kk] : 0.0f;
            Bs[kk][row] = wb[(size_t)row * D_MODEL + k0 + kk];
        }
        __syncthreads();
#pragma unroll
        for (int kk = 0; kk < TKK; kk++) {
            float4 a = *(const float4*)&As[kk][ty * 4];
            float4 b = *(const float4*)&Bs[kk][tx * 4];
            float av[4] = {a.x, a.y, a.z, a.w};
            float bv[4] = {b.x, b.y, b.z, b.w};
#pragma unroll
            for (int i = 0; i < 4; i++)
#pragma unroll
                for (int j = 0; j < 4; j++)
                    acc[i][j] = fmaf(av[i], bv[j], acc[i][j]);
        }
        __syncthreads();
    }

#pragma unroll
    for (int i = 0; i < 4; i++) {
        int row = ty * 4 + i;
        int t = tok[row];
        if (t < 0) continue;
        float* hp = &g_H[(size_t)(r0 + row) * D_FF + f0 + tx * 4];
        const float* bp = &b1[e * D_FF + f0 + tx * 4];
#pragma unroll
        for (int j = 0; j < 4; j++) {
            float v = acc[i][j] + bp[j];
            v = 0.5f * v * (1.0f + erff(v * 0.70710678118654752f));  // exact gelu
            hp[j] = v;
        }
    }
}

// ---------------- pass 2: out += gate * (H @ w2[e]^T + b2[e]) ------------
__global__ void __launch_bounds__(256) k_ffn2(const float* __restrict__ w2,
                                              const float* __restrict__ b2,
                                              float* __restrict__ out) {
    int e = g_tile_expert[blockIdx.x];
    if (e < 0) return;
    int r0 = blockIdx.x * TM;
    int c0 = blockIdx.y * TN;

    __shared__ float As[TKK][TM];
    __shared__ float Bs[TKK][TN];
    __shared__ int   tok[TM];
    __shared__ float gate[TM];

    int tid = threadIdx.x;
    if (tid < TM) {
        tok[tid]  = g_sorted_token[r0 + tid];
        gate[tid] = g_sorted_gate[r0 + tid];
    }
    __syncthreads();
    if (tok[0] < 0) return;

    float acc[4][4] = {};
    int ty = tid >> 4, tx = tid & 15;
    const float* ha = g_H + (size_t)r0 * D_FF;
    const float* wb = w2 + ((size_t)e * D_MODEL + c0) * D_FF;

    for (int k0 = 0; k0 < D_FF; k0 += TKK) {
#pragma unroll
        for (int i = 0; i < 4; i++) {
            int li = tid + i * 256;
            int row = li >> 4, kk = li & 15;
            As[kk][row] = ha[(size_t)row * D_FF + k0 + kk];          // pad rows: garbage, unused
            Bs[kk][row] = wb[(size_t)row * D_FF + k0 + kk];
        }
        __syncthreads();
#pragma unroll
        for (int kk = 0; kk < TKK; kk++) {
            float4 a = *(const float4*)&As[kk][ty * 4];
            float4 b = *(const float4*)&Bs[kk][tx * 4];
            float av[4] = {a.x, a.y, a.z, a.w};
            float bv[4] = {b.x, b.y, b.z, b.w};
#pragma unroll
            for (int i = 0; i < 4; i++)
#pragma unroll
                for (int j = 0; j < 4; j++)
                    acc[i][j] = fmaf(av[i], bv[j], acc[i][j]);
        }
        __syncthreads();
    }

#pragma unroll
    for (int i = 0; i < 4; i++) {
        int row = ty * 4 + i;
        int t = tok[row];
        if (t < 0) continue;
        float g = gate[row];
        const float* bp = &b2[e * D_MODEL + c0 + tx * 4];
        float* op = &out[(size_t)t * D_MODEL + c0 + tx * 4];
#pragma unroll
        for (int j = 0; j < 4; j++) {
            float v = g * (acc[i][j] + bp[j]);
            atomicAdd(&op[j], v);   // exactly 2 commutative adds per element
        }
    }
}

// ---------------- launch ----------------
extern "C" void kernel_launch(void* const* d_in, const int* in_sizes, int n_in,
                              void* d_out, int out_size) {
    (void)in_sizes; (void)n_in; (void)out_size;
    const float* x  = (const float*)d_in[0];
    const float* rw = (const float*)d_in[1];
    const float* rb = (const float*)d_in[2];
    const float* w1 = (const float*)d_in[3];
    const float* b1 = (const float*)d_in[4];
    const float* w2 = (const float*)d_in[5];
    const float* b2 = (const float*)d_in[6];
    float* out = (float*)d_out;

    k_init<<<1024, 256>>>(out);
    k_router<<<T_TOKENS / 8, 256>>>(x, rw, rb);
    k_setup<<<1, 1>>>();
    k_scatter<<<(NPAIRS + 255) / 256, 256>>>();
    k_ffn1<<<dim3(MAX_TILES, D_FF / TN), 256>>>(x, w1, b1);
    k_ffn2<<<dim3(MAX_TILES, D_MODEL / TN), 256>>>(w2, b2, out);
}

// round 9
// speedup vs baseline: 1.0019x; 1.0019x over previous
#include <cuda_runtime.h>
#include <math.h>

#define D_MODEL  1024
#define D_FF     4096
#define N_EXPERTS 8
#define T_TOKENS 8192
#define TOPK     2
#define NPAIRS   (T_TOKENS * TOPK)          // 16384

#define TM  64
#define TN  64
#define TKK 16
#define ROWS_CAP  (NPAIRS + N_EXPERTS * TM) // 16896 (each expert segment padded to TM)
#define MAX_TILES (ROWS_CAP / TM)           // 264

// ---------------- static device scratch (allocation-free) ----------------
__device__ float g_H[(size_t)ROWS_CAP * D_FF];   // intermediate gelu(x@w1^T)
__device__ int   g_sorted_token[ROWS_CAP];       // pair rows grouped by expert, -1 = pad
__device__ float g_sorted_gate[ROWS_CAP];
__device__ int   g_off[N_EXPERTS + 1];           // padded segment offsets
__device__ int   g_count[N_EXPERTS];
__device__ int   g_tile_expert[MAX_TILES];       // expert per 64-row tile, -1 = unused
__device__ int   g_pair_expert[NPAIRS];
__device__ float g_pair_gate[NPAIRS];
__device__ int   g_pair_rank[NPAIRS];

// ---------------- init: zero out, counts, pad markers ----------------
__global__ void k_init(float* __restrict__ out) {
    int stride = gridDim.x * blockDim.x;
    int i0 = blockIdx.x * blockDim.x + threadIdx.x;
    const int n = T_TOKENS * D_MODEL;
    for (int i = i0; i < n; i += stride) out[i] = 0.0f;
    for (int i = i0; i < ROWS_CAP; i += stride) g_sorted_token[i] = -1;
    if (i0 < N_EXPERTS) g_count[i0] = 0;
}

// ---------------- router: one warp per token ----------------
__global__ void k_router(const float* __restrict__ x,
                         const float* __restrict__ rw,
                         const float* __restrict__ rb) {
    int warp = (blockIdx.x * blockDim.x + threadIdx.x) >> 5;
    int lane = threadIdx.x & 31;
    if (warp >= T_TOKENS) return;
    const float* xt = x + (size_t)warp * D_MODEL;

    float lg[N_EXPERTS];
#pragma unroll
    for (int e = 0; e < N_EXPERTS; e++) {
        const float* we = rw + e * D_MODEL;
        float s = 0.0f;
        for (int d = lane; d < D_MODEL; d += 32) s = fmaf(xt[d], we[d], s);
#pragma unroll
        for (int o = 16; o > 0; o >>= 1) s += __shfl_down_sync(0xffffffffu, s, o);
        lg[e] = s;
    }
    if (lane == 0) {
        float m = -1e30f;
#pragma unroll
        for (int e = 0; e < N_EXPERTS; e++) { lg[e] += rb[e]; m = fmaxf(m, lg[e]); }
        float p[N_EXPERTS];
#pragma unroll
        for (int e = 0; e < N_EXPERTS; e++) p[e] = expf(lg[e] - m);
        int i1 = 0;
#pragma unroll
        for (int e = 1; e < N_EXPERTS; e++) if (p[e] > p[i1]) i1 = e;   // ties -> lower idx
        int i2 = (i1 == 0) ? 1 : 0;
#pragma unroll
        for (int e = 0; e < N_EXPERTS; e++) if (e != i1 && p[e] > p[i2]) i2 = e;
        float s2 = p[i1] + p[i2];
        g_pair_expert[warp * 2 + 0] = i1;
        g_pair_expert[warp * 2 + 1] = i2;
        g_pair_gate[warp * 2 + 0] = p[i1] / s2;
        g_pair_gate[warp * 2 + 1] = p[i2] / s2;
        g_pair_rank[warp * 2 + 0] = atomicAdd(&g_count[i1], 1);
        g_pair_rank[warp * 2 + 1] = atomicAdd(&g_count[i2], 1);
    }
}

// ---------------- offsets + tile->expert map (single thread, trivial) ----
__global__ void k_setup() {
    int off = 0;
    for (int e = 0; e < N_EXPERTS; e++) {
        g_off[e] = off;
        off += (g_count[e] + TM - 1) / TM * TM;
    }
    g_off[N_EXPERTS] = off;
    int nt = off / TM;
    for (int i = 0; i < MAX_TILES; i++) {
        int te = -1;
        if (i < nt) {
            int r = i * TM;
            for (int e = 0; e < N_EXPERTS; e++)
                if (r >= g_off[e] && r < g_off[e + 1]) { te = e; break; }
        }
        g_tile_expert[i] = te;
    }
}

// ---------------- scatter pairs into expert-grouped rows ----------------
__global__ void k_scatter() {
    int i = blockIdx.x * blockDim.x + threadIdx.x;
    if (i >= NPAIRS) return;
    int e = g_pair_expert[i];
    int r = g_off[e] + g_pair_rank[i];
    g_sorted_token[r] = i >> 1;
    g_sorted_gate[r]  = g_pair_gate[i];
}

// ---------------- pass 1: H = gelu(X_e @ w1[e]^T + b1[e]) ----------------
__global__ void __launch_bounds__(256) k_ffn1(const float* __restrict__ x,
                                              const float* __restrict__ w1,
                                              const float* __restrict__ b1) {
    int e = g_tile_expert[blockIdx.x];
    if (e < 0) return;
    int r0 = blockIdx.x * TM;
    int f0 = blockIdx.y * TN;

    __shared__ float As[TKK][TM];
    __shared__ float Bs[TKK][TN];
    __shared__ int   tok[TM];

    int tid = threadIdx.x;
    if (tid < TM) tok[tid] = g_sorted_token[r0 + tid];
    __syncthreads();
    if (tok[0] < 0) return;   // fully padded tile (padding is at segment tail)

    float acc[4][4] = {};
    int ty = tid >> 4, tx = tid & 15;
    const float* wb = w1 + ((size_t)e * D_FF + f0) * D_MODEL;

    for (int k0 = 0; k0 < D_MODEL; k0 += TKK) {
#pragma unroll
        for (int i = 0; i < 4; i++) {
            int li = tid + i * 256;
            int row = li >> 4, kk = li & 15;
            int t = tok[row];
            As[kk][row] = (t >= 0) ? x[(size_t)t * D_MODEL + k0 + kk] : 0.0f;
            Bs[kk][row] = wb[(size_t)row * D_MODEL + k0 + kk];
        }
        __syncthreads();
#pragma unroll
        for (int kk = 0; kk < TKK; kk++) {
            float4 a = *(const float4*)&As[kk][ty * 4];
            float4 b = *(const float4*)&Bs[kk][tx * 4];
            float av[4] = {a.x, a.y, a.z, a.w};
            float bv[4] = {b.x, b.y, b.z, b.w};
#pragma unroll
            for (int i = 0; i < 4; i++)
#pragma unroll
                for (int j = 0; j < 4; j++)
                    acc[i][j] = fmaf(av[i], bv[j], acc[i][j]);
        }
        __syncthreads();
    }

#pragma unroll
    for (int i = 0; i < 4; i++) {
        int row = ty * 4 + i;
        int t = tok[row];
        if (t < 0) continue;
        float* hp = &g_H[(size_t)(r0 + row) * D_FF + f0 + tx * 4];
        const float* bp = &b1[e * D_FF + f0 + tx * 4];
#pragma unroll
        for (int j = 0; j < 4; j++) {
            float v = acc[i][j] + bp[j];
            v = 0.5f * v * (1.0f + erff(v * 0.70710678118654752f));  // exact gelu
            hp[j] = v;
        }
    }
}

// ---------------- pass 2: out += gate * (H @ w2[e]^T + b2[e]) ------------
__global__ void __launch_bounds__(256) k_ffn2(const float* __restrict__ w2,
                                              const float* __restrict__ b2,
                                              float* __restrict__ out) {
    int e = g_tile_expert[blockIdx.x];
    if (e < 0) return;
    int r0 = blockIdx.x * TM;
    int c0 = blockIdx.y * TN;

    __shared__ float As[TKK][TM];
    __shared__ float Bs[TKK][TN];
    __shared__ int   tok[TM];
    __shared__ float gate[TM];

    int tid = threadIdx.x;
    if (tid < TM) {
        tok[tid]  = g_sorted_token[r0 + tid];
        gate[tid] = g_sorted_gate[r0 + tid];
    }
    __syncthreads();
    if (tok[0] < 0) return;

    float acc[4][4] = {};
    int ty = tid >> 4, tx = tid & 15;
    const float* ha = g_H + (size_t)r0 * D_FF;
    const float* wb = w2 + ((size_t)e * D_MODEL + c0) * D_FF;

    for (int k0 = 0; k0 < D_FF; k0 += TKK) {
#pragma unroll
        for (int i = 0; i < 4; i++) {
            int li = tid + i * 256;
            int row = li >> 4, kk = li & 15;
            As[kk][row] = ha[(size_t)row * D_FF + k0 + kk];          // pad rows: garbage, unused
            Bs[kk][row] = wb[(size_t)row * D_FF + k0 + kk];
        }
        __syncthreads();
#pragma unroll
        for (int kk = 0; kk < TKK; kk++) {
            float4 a = *(const float4*)&As[kk][ty * 4];
            float4 b = *(const float4*)&Bs[kk][tx * 4];
            float av[4] = {a.x, a.y, a.z, a.w};
            float bv[4] = {b.x, b.y, b.z, b.w};
#pragma unroll
            for (int i = 0; i < 4; i++)
#pragma unroll
                for (int j = 0; j < 4; j++)
                    acc[i][j] = fmaf(av[i], bv[j], acc[i][j]);
        }
        __syncthreads();
    }

#pragma unroll
    for (int i = 0; i < 4; i++) {
        int row = ty * 4 + i;
        int t = tok[row];
        if (t < 0) continue;
        float g = gate[row];
        const float* bp = &b2[e * D_MODEL + c0 + tx * 4];
        float* op = &out[(size_t)t * D_MODEL + c0 + tx * 4];
#pragma unroll
        for (int j = 0; j < 4; j++) {
            float v = g * (acc[i][j] + bp[j]);
            atomicAdd(&op[j], v);   // exactly 2 commutative adds per element
        }
    }
}

// ---------------- launch ----------------
extern "C" void kernel_launch(void* const* d_in, const int* in_sizes, int n_in,
                              void* d_out, int out_size) {
    (void)in_sizes; (void)n_in; (void)out_size;
    const float* x  = (const float*)d_in[0];
    const float* rw = (const float*)d_in[1];
    const float* rb = (const float*)d_in[2];
    const float* w1 = (const float*)d_in[3];
    const float* b1 = (const float*)d_in[4];
    const float* w2 = (const float*)d_in[5];
    const float* b2 = (const float*)d_in[6];
    float* out = (float*)d_out;

    k_init<<<1024, 256>>>(out);
    k_router<<<T_TOKENS / 8, 256>>>(x, rw, rb);
    k_setup<<<1, 1>>>();
    k_scatter<<<(NPAIRS + 255) / 256, 256>>>();
    k_ffn1<<<dim3(MAX_TILES, D_FF / TN), 256>>>(x, w1, b1);
    k_ffn2<<<dim3(MAX_TILES, D_MODEL / TN), 256>>>(w2, b2, out);
}

// round 10
// speedup vs baseline: 4.8210x; 4.8118x over previous
#include <cuda_runtime.h>
#include <math.h>

#define D_MODEL  1024
#define D_FF     4096
#define N_EXPERTS 8
#define T_TOKENS 8192
#define TOPK     2
#define NPAIRS   (T_TOKENS * TOPK)          // 16384

#define TM  128
#define TN  64
#define TKK 16
#define SK  (TKK + 4)                        // smem row stride (words) -> conflict-free frag reads
#define ROWS_CAP  (NPAIRS + N_EXPERTS * TM) // 17408 (each expert segment padded to TM)
#define MAX_TILES (ROWS_CAP / TM)           // 136

// ---------------- static device scratch (allocation-free) ----------------
__device__ float g_H[(size_t)ROWS_CAP * D_FF];   // intermediate gelu(x@w1^T)
__device__ int   g_sorted_token[ROWS_CAP];       // pair rows grouped by expert, -1 = pad
__device__ float g_sorted_gate[ROWS_CAP];
__device__ int   g_off[N_EXPERTS + 1];           // padded segment offsets
__device__ int   g_count[N_EXPERTS];
__device__ int   g_tile_expert[MAX_TILES];       // expert per 128-row tile, -1 = unused
__device__ int   g_pair_expert[NPAIRS];
__device__ float g_pair_gate[NPAIRS];
__device__ int   g_pair_rank[NPAIRS];

// ---------------- tf32 helpers ----------------
__device__ __forceinline__ unsigned f2tf(float f) {
    unsigned u;
    asm("cvt.rna.tf32.f32 %0, %1;" : "=r"(u) : "f"(f));
    return u;
}

__device__ __forceinline__ void mma_tf32(float* c, const unsigned* a, const unsigned* b) {
    asm volatile(
        "mma.sync.aligned.m16n8k8.row.col.f32.tf32.tf32.f32 "
        "{%0,%1,%2,%3}, {%4,%5,%6,%7}, {%8,%9}, {%0,%1,%2,%3};"
        : "+f"(c[0]), "+f"(c[1]), "+f"(c[2]), "+f"(c[3])
        : "r"(a[0]), "r"(a[1]), "r"(a[2]), "r"(a[3]), "r"(b[0]), "r"(b[1]));
}

// ---------------- init: zero out, counts, pad markers ----------------
__global__ void k_init(float* __restrict__ out) {
    int stride = gridDim.x * blockDim.x;
    int i0 = blockIdx.x * blockDim.x + threadIdx.x;
    const int n = T_TOKENS * D_MODEL;
    for (int i = i0; i < n; i += stride) out[i] = 0.0f;
    for (int i = i0; i < ROWS_CAP; i += stride) g_sorted_token[i] = -1;
    if (i0 < N_EXPERTS) g_count[i0] = 0;
}

// ---------------- router: one warp per token ----------------
__global__ void k_router(const float* __restrict__ x,
                         const float* __restrict__ rw,
                         const float* __restrict__ rb) {
    int warp = (blockIdx.x * blockDim.x + threadIdx.x) >> 5;
    int lane = threadIdx.x & 31;
    if (warp >= T_TOKENS) return;
    const float* xt = x + (size_t)warp * D_MODEL;

    float lg[N_EXPERTS];
#pragma unroll
    for (int e = 0; e < N_EXPERTS; e++) {
        const float* we = rw + e * D_MODEL;
        float s = 0.0f;
        for (int d = lane; d < D_MODEL; d += 32) s = fmaf(xt[d], we[d], s);
#pragma unroll
        for (int o = 16; o > 0; o >>= 1) s += __shfl_down_sync(0xffffffffu, s, o);
        lg[e] = s;
    }
    if (lane == 0) {
        float m = -1e30f;
#pragma unroll
        for (int e = 0; e < N_EXPERTS; e++) { lg[e] += rb[e]; m = fmaxf(m, lg[e]); }
        float p[N_EXPERTS];
#pragma unroll
        for (int e = 0; e < N_EXPERTS; e++) p[e] = expf(lg[e] - m);
        int i1 = 0;
#pragma unroll
        for (int e = 1; e < N_EXPERTS; e++) if (p[e] > p[i1]) i1 = e;   // ties -> lower idx
        int i2 = (i1 == 0) ? 1 : 0;
#pragma unroll
        for (int e = 0; e < N_EXPERTS; e++) if (e != i1 && p[e] > p[i2]) i2 = e;
        float s2 = p[i1] + p[i2];
        g_pair_expert[warp * 2 + 0] = i1;
        g_pair_expert[warp * 2 + 1] = i2;
        g_pair_gate[warp * 2 + 0] = p[i1] / s2;
        g_pair_gate[warp * 2 + 1] = p[i2] / s2;
        g_pair_rank[warp * 2 + 0] = atomicAdd(&g_count[i1], 1);
        g_pair_rank[warp * 2 + 1] = atomicAdd(&g_count[i2], 1);
    }
}

// ---------------- offsets + tile->expert map (single thread, trivial) ----
__global__ void k_setup() {
    int off = 0;
    for (int e = 0; e < N_EXPERTS; e++) {
        g_off[e] = off;
        off += (g_count[e] + TM - 1) / TM * TM;
    }
    g_off[N_EXPERTS] = off;
    int nt = off / TM;
    for (int i = 0; i < MAX_TILES; i++) {
        int te = -1;
        if (i < nt) {
            int r = i * TM;
            for (int e = 0; e < N_EXPERTS; e++)
                if (r >= g_off[e] && r < g_off[e + 1]) { te = e; break; }
        }
        g_tile_expert[i] = te;
    }
}

// ---------------- scatter pairs into expert-grouped rows ----------------
__global__ void k_scatter() {
    int i = blockIdx.x * blockDim.x + threadIdx.x;
    if (i >= NPAIRS) return;
    int e = g_pair_expert[i];
    int r = g_off[e] + g_pair_rank[i];
    g_sorted_token[r] = i >> 1;
    g_sorted_gate[r]  = g_pair_gate[i];
}

// ---------------- pass 1: H = gelu(X_e @ w1[e]^T + b1[e]) ----------------
// CTA tile 128x64x16, tf32 mma.sync m16n8k8, 8 warps in 4(M) x 2(N).
__global__ void __launch_bounds__(256) k_ffn1(const float* __restrict__ x,
                                              const float* __restrict__ w1,
                                              const float* __restrict__ b1) {
    int e = g_tile_expert[blockIdx.x];
    if (e < 0) return;
    int r0 = blockIdx.x * TM;
    int f0 = blockIdx.y * TN;

    __shared__ unsigned As[TM][SK];   // m-major, tf32-converted
    __shared__ unsigned Bs[TN][SK];
    __shared__ int tok[TM];

    int tid = threadIdx.x;
    if (tid < TM) tok[tid] = g_sorted_token[r0 + tid];
    __syncthreads();
    if (tok[0] < 0) return;   // fully padded tile

    int lane = tid & 31, wid = tid >> 5;
    int wm = (wid & 3) * 32;          // warp M offset (0..96)
    int wn = (wid >> 2) * 32;         // warp N offset (0 or 32)
    int g = lane >> 2, q = lane & 3;

    float acc[2][4][4] = {};
    const float* wb = w1 + ((size_t)e * D_FF + f0) * D_MODEL;

    // A-load indices: 512 float4 / 256 thr = 2 each
    for (int k0 = 0; k0 < D_MODEL; k0 += TKK) {
#pragma unroll
        for (int i = 0; i < 2; i++) {
            int idx = tid + i * 256;
            int row = idx >> 2, c = idx & 3;
            int t = tok[row];
            float4 v = (t >= 0) ? *(const float4*)&x[(size_t)t * D_MODEL + k0 + c * 4]
                                : make_float4(0.f, 0.f, 0.f, 0.f);
            As[row][c * 4 + 0] = f2tf(v.x);
            As[row][c * 4 + 1] = f2tf(v.y);
            As[row][c * 4 + 2] = f2tf(v.z);
            As[row][c * 4 + 3] = f2tf(v.w);
        }
        {
            int row = tid >> 2, c = tid & 3;
            float4 v = *(const float4*)&wb[(size_t)row * D_MODEL + k0 + c * 4];
            Bs[row][c * 4 + 0] = f2tf(v.x);
            Bs[row][c * 4 + 1] = f2tf(v.y);
            Bs[row][c * 4 + 2] = f2tf(v.z);
            Bs[row][c * 4 + 3] = f2tf(v.w);
        }
        __syncthreads();
#pragma unroll
        for (int k8 = 0; k8 < TKK; k8 += 8) {
            unsigned a[2][4], b[4][2];
#pragma unroll
            for (int mi = 0; mi < 2; mi++) {
                int rbase = wm + mi * 16 + g;
                a[mi][0] = As[rbase][k8 + q];
                a[mi][1] = As[rbase + 8][k8 + q];
                a[mi][2] = As[rbase][k8 + q + 4];
                a[mi][3] = As[rbase + 8][k8 + q + 4];
            }
#pragma unroll
            for (int ni = 0; ni < 4; ni++) {
                int cbase = wn + ni * 8 + g;
                b[ni][0] = Bs[cbase][k8 + q];
                b[ni][1] = Bs[cbase][k8 + q + 4];
            }
#pragma unroll
            for (int mi = 0; mi < 2; mi++)
#pragma unroll
                for (int ni = 0; ni < 4; ni++)
                    mma_tf32(acc[mi][ni], a[mi], b[ni]);
        }
        __syncthreads();
    }

    // epilogue: bias + exact gelu, float2 stores to g_H
#pragma unroll
    for (int mi = 0; mi < 2; mi++) {
#pragma unroll
        for (int half = 0; half < 2; half++) {
            int row = wm + mi * 16 + g + half * 8;
            int t = tok[row];
            if (t < 0) continue;
#pragma unroll
            for (int ni = 0; ni < 4; ni++) {
                int col = f0 + wn + ni * 8 + q * 2;
                float v0 = acc[mi][ni][half * 2 + 0] + b1[e * D_FF + col];
                float v1 = acc[mi][ni][half * 2 + 1] + b1[e * D_FF + col + 1];
                v0 = 0.5f * v0 * (1.0f + erff(v0 * 0.70710678118654752f));
                v1 = 0.5f * v1 * (1.0f + erff(v1 * 0.70710678118654752f));
                *(float2*)&g_H[(size_t)(r0 + row) * D_FF + col] = make_float2(v0, v1);
            }
        }
    }
}

// ---------------- pass 2: out += gate * (H @ w2[e]^T + b2[e]) ------------
__global__ void __launch_bounds__(256) k_ffn2(const float* __restrict__ w2,
                                              const float* __restrict__ b2,
                                              float* __restrict__ out) {
    int e = g_tile_expert[blockIdx.x];
    if (e < 0) return;
    int r0 = blockIdx.x * TM;
    int c0 = blockIdx.y * TN;

    __shared__ unsigned As[TM][SK];
    __shared__ unsigned Bs[TN][SK];
    __shared__ int tok[TM];
    __shared__ float gate[TM];

    int tid = threadIdx.x;
    if (tid < TM) {
        tok[tid]  = g_sorted_token[r0 + tid];
        gate[tid] = g_sorted_gate[r0 + tid];
    }
    __syncthreads();
    if (tok[0] < 0) return;

    int lane = tid & 31, wid = tid >> 5;
    int wm = (wid & 3) * 32;
    int wn = (wid >> 2) * 32;
    int g = lane >> 2, q = lane & 3;

    float acc[2][4][4] = {};
    const float* ha = g_H + (size_t)r0 * D_FF;
    const float* wb = w2 + ((size_t)e * D_MODEL + c0) * D_FF;

    for (int k0 = 0; k0 < D_FF; k0 += TKK) {
#pragma unroll
        for (int i = 0; i < 2; i++) {
            int idx = tid + i * 256;
            int row = idx >> 2, c = idx & 3;
            // pad rows: stale-but-finite data, results discarded in epilogue
            float4 v = *(const float4*)&ha[(size_t)row * D_FF + k0 + c * 4];
            As[row][c * 4 + 0] = f2tf(v.x);
            As[row][c * 4 + 1] = f2tf(v.y);
            As[row][c * 4 + 2] = f2tf(v.z);
            As[row][c * 4 + 3] = f2tf(v.w);
        }
        {
            int row = tid >> 2, c = tid & 3;
            float4 v = *(const float4*)&wb[(size_t)row * D_FF + k0 + c * 4];
            Bs[row][c * 4 + 0] = f2tf(v.x);
            Bs[row][c * 4 + 1] = f2tf(v.y);
            Bs[row][c * 4 + 2] = f2tf(v.z);
            Bs[row][c * 4 + 3] = f2tf(v.w);
        }
        __syncthreads();
#pragma unroll
        for (int k8 = 0; k8 < TKK; k8 += 8) {
            unsigned a[2][4], b[4][2];
#pragma unroll
            for (int mi = 0; mi < 2; mi++) {
                int rbase = wm + mi * 16 + g;
                a[mi][0] = As[rbase][k8 + q];
                a[mi][1] = As[rbase + 8][k8 + q];
                a[mi][2] = As[rbase][k8 + q + 4];
                a[mi][3] = As[rbase + 8][k8 + q + 4];
            }
#pragma unroll
            for (int ni = 0; ni < 4; ni++) {
                int cbase = wn + ni * 8 + g;
                b[ni][0] = Bs[cbase][k8 + q];
                b[ni][1] = Bs[cbase][k8 + q + 4];
            }
#pragma unroll
            for (int mi = 0; mi < 2; mi++)
#pragma unroll
                for (int ni = 0; ni < 4; ni++)
                    mma_tf32(acc[mi][ni], a[mi], b[ni]);
        }
        __syncthreads();
    }

    // epilogue: gate * (acc + bias), atomicAdd into out (2 commutative adds/elem)
#pragma unroll
    for (int mi = 0; mi < 2; mi++) {
#pragma unroll
        for (int half = 0; half < 2; half++) {
            int row = wm + mi * 16 + g + half * 8;
            int t = tok[row];
            if (t < 0) continue;
            float gw = gate[row];
#pragma unroll
            for (int ni = 0; ni < 4; ni++) {
                int col = c0 + wn + ni * 8 + q * 2;
                float v0 = gw * (acc[mi][ni][half * 2 + 0] + b2[e * D_MODEL + col]);
                float v1 = gw * (acc[mi][ni][half * 2 + 1] + b2[e * D_MODEL + col + 1]);
                atomicAdd(&out[(size_t)t * D_MODEL + col], v0);
                atomicAdd(&out[(size_t)t * D_MODEL + col + 1], v1);
            }
        }
    }
}

// ---------------- launch ----------------
extern "C" void kernel_launch(void* const* d_in, const int* in_sizes, int n_in,
                              void* d_out, int out_size) {
    (void)in_sizes; (void)n_in; (void)out_size;
    const float* x  = (const float*)d_in[0];
    const float* rw = (const float*)d_in[1];
    const float* rb = (const float*)d_in[2];
    const float* w1 = (const float*)d_in[3];
    const float* b1 = (const float*)d_in[4];
    const float* w2 = (const float*)d_in[5];
    const float* b2 = (const float*)d_in[6];
    float* out = (float*)d_out;

    k_init<<<1024, 256>>>(out);
    k_router<<<T_TOKENS / 8, 256>>>(x, rw, rb);
    k_setup<<<1, 1>>>();
    k_scatter<<<(NPAIRS + 255) / 256, 256>>>();
    k_ffn1<<<dim3(MAX_TILES, D_FF / TN), 256>>>(x, w1, b1);
    k_ffn2<<<dim3(MAX_TILES, D_MODEL / TN), 256>>>(w2, b2, out);
}

// round 11
// speedup vs baseline: 5.6914x; 1.1805x over previous
#include <cuda_runtime.h>
#include <math.h>

#define D_MODEL  1024
#define D_FF     4096
#define N_EXPERTS 8
#define T_TOKENS 8192
#define TOPK     2
#define NPAIRS   (T_TOKENS * TOPK)          // 16384

#define TM  128
#define TN  64
#define TKK 16
#define SK  (TKK + 4)                        // smem row stride (words) -> conflict-free frag reads
#define STAGES 2
#define ROWS_CAP  (NPAIRS + N_EXPERTS * TM) // 17408
#define MAX_TILES (ROWS_CAP / TM)           // 136

// ---------------- static device scratch (allocation-free) ----------------
__device__ float g_H[(size_t)ROWS_CAP * D_FF];   // gelu(x@w1^T); pad rows stay 0 (static zero-init)
__device__ int   g_sorted_token[ROWS_CAP];
__device__ float g_sorted_gate[ROWS_CAP];
__device__ int   g_off[N_EXPERTS + 1];
__device__ int   g_count[N_EXPERTS];
__device__ int   g_tile_expert[MAX_TILES];
__device__ int   g_pair_expert[NPAIRS];
__device__ float g_pair_gate[NPAIRS];
__device__ int   g_pair_rank[NPAIRS];

// ---------------- helpers ----------------
__device__ __forceinline__ unsigned f2tf(float f) {
    unsigned u;
    asm("cvt.rna.tf32.f32 %0, %1;" : "=r"(u) : "f"(f));
    return u;
}

__device__ __forceinline__ void mma_tf32(float* c, const unsigned* a, const unsigned* b) {
    asm volatile(
        "mma.sync.aligned.m16n8k8.row.col.f32.tf32.tf32.f32 "
        "{%0,%1,%2,%3}, {%4,%5,%6,%7}, {%8,%9}, {%0,%1,%2,%3};"
        : "+f"(c[0]), "+f"(c[1]), "+f"(c[2]), "+f"(c[3])
        : "r"(a[0]), "r"(a[1]), "r"(a[2]), "r"(a[3]), "r"(b[0]), "r"(b[1]));
}

__device__ __forceinline__ void cp16(unsigned dst, const void* src, int src_bytes) {
    asm volatile("cp.async.cg.shared.global [%0], [%1], 16, %2;"
                 :: "r"(dst), "l"(src), "r"(src_bytes));
}
__device__ __forceinline__ void cp_commit() {
    asm volatile("cp.async.commit_group;");
}
template <int N>
__device__ __forceinline__ void cp_wait() {
    asm volatile("cp.async.wait_group %0;" :: "n"(N));
}

// ---------------- init ----------------
__global__ void k_init(float* __restrict__ out) {
    int stride = gridDim.x * blockDim.x;
    int i0 = blockIdx.x * blockDim.x + threadIdx.x;
    const int n = T_TOKENS * D_MODEL;
    for (int i = i0; i < n; i += stride) out[i] = 0.0f;
    for (int i = i0; i < ROWS_CAP; i += stride) g_sorted_token[i] = -1;
    if (i0 < N_EXPERTS) g_count[i0] = 0;
}

// ---------------- router: one warp per token ----------------
__global__ void k_router(const float* __restrict__ x,
                         const float* __restrict__ rw,
                         const float* __restrict__ rb) {
    int warp = (blockIdx.x * blockDim.x + threadIdx.x) >> 5;
    int lane = threadIdx.x & 31;
    if (warp >= T_TOKENS) return;
    const float* xt = x + (size_t)warp * D_MODEL;

    float lg[N_EXPERTS];
#pragma unroll
    for (int e = 0; e < N_EXPERTS; e++) {
        const float* we = rw + e * D_MODEL;
        float s = 0.0f;
        for (int d = lane; d < D_MODEL; d += 32) s = fmaf(xt[d], we[d], s);
#pragma unroll
        for (int o = 16; o > 0; o >>= 1) s += __shfl_down_sync(0xffffffffu, s, o);
        lg[e] = s;
    }
    if (lane == 0) {
        float m = -1e30f;
#pragma unroll
        for (int e = 0; e < N_EXPERTS; e++) { lg[e] += rb[e]; m = fmaxf(m, lg[e]); }
        float p[N_EXPERTS];
#pragma unroll
        for (int e = 0; e < N_EXPERTS; e++) p[e] = expf(lg[e] - m);
        int i1 = 0;
#pragma unroll
        for (int e = 1; e < N_EXPERTS; e++) if (p[e] > p[i1]) i1 = e;
        int i2 = (i1 == 0) ? 1 : 0;
#pragma unroll
        for (int e = 0; e < N_EXPERTS; e++) if (e != i1 && p[e] > p[i2]) i2 = e;
        float s2 = p[i1] + p[i2];
        g_pair_expert[warp * 2 + 0] = i1;
        g_pair_expert[warp * 2 + 1] = i2;
        g_pair_gate[warp * 2 + 0] = p[i1] / s2;
        g_pair_gate[warp * 2 + 1] = p[i2] / s2;
        g_pair_rank[warp * 2 + 0] = atomicAdd(&g_count[i1], 1);
        g_pair_rank[warp * 2 + 1] = atomicAdd(&g_count[i2], 1);
    }
}

// ---------------- offsets + tile->expert map ----------------
__global__ void k_setup() {
    int off = 0;
    for (int e = 0; e < N_EXPERTS; e++) {
        g_off[e] = off;
        off += (g_count[e] + TM - 1) / TM * TM;
    }
    g_off[N_EXPERTS] = off;
    int nt = off / TM;
    for (int i = 0; i < MAX_TILES; i++) {
        int te = -1;
        if (i < nt) {
            int r = i * TM;
            for (int e = 0; e < N_EXPERTS; e++)
                if (r >= g_off[e] && r < g_off[e + 1]) { te = e; break; }
        }
        g_tile_expert[i] = te;
    }
}

// ---------------- scatter ----------------
__global__ void k_scatter() {
    int i = blockIdx.x * blockDim.x + threadIdx.x;
    if (i >= NPAIRS) return;
    int e = g_pair_expert[i];
    int r = g_off[e] + g_pair_rank[i];
    g_sorted_token[r] = i >> 1;
    g_sorted_gate[r]  = g_pair_gate[i];
}

// ======================================================================
// pass 1: H = gelu(X_e @ w1[e]^T + b1[e])
// CTA tile 128x64x16, tf32 mma.sync, cp.async double-buffered
// ======================================================================
__global__ void __launch_bounds__(256) k_ffn1(const float* __restrict__ x,
                                              const float* __restrict__ w1,
                                              const float* __restrict__ b1) {
    int e = g_tile_expert[blockIdx.x];
    if (e < 0) return;
    int r0 = blockIdx.x * TM;
    int f0 = blockIdx.y * TN;

    __shared__ float As[STAGES][TM][SK];
    __shared__ float Bs[STAGES][TN][SK];
    __shared__ int tok[TM];

    int tid = threadIdx.x;
    if (tid < TM) tok[tid] = g_sorted_token[r0 + tid];
    __syncthreads();
    if (tok[0] < 0) return;

    int lane = tid & 31, wid = tid >> 5;
    int wm = (wid & 3) * 32;          // warp M offset
    int wn = (wid >> 2) * 32;         // warp N offset
    int g = lane >> 2, q = lane & 3;

    // per-thread load slots (k-invariant)
    int rowA0 = tid >> 2, cA = tid & 3;          // A slot 0
    int rowA1 = rowA0 + 64;                      // A slot 1
    int t0 = tok[rowA0], t1 = tok[rowA1];
    const float* srcA0 = x + (t0 >= 0 ? (size_t)t0 * D_MODEL : 0) + cA * 4;
    const float* srcA1 = x + (t1 >= 0 ? (size_t)t1 * D_MODEL : 0) + cA * 4;
    int szA0 = t0 >= 0 ? 16 : 0, szA1 = t1 >= 0 ? 16 : 0;
    const float* wb = w1 + ((size_t)e * D_FF + f0) * D_MODEL;
    const float* srcB = wb + (size_t)rowA0 * D_MODEL + cA * 4;

    unsigned dA0[STAGES], dA1[STAGES], dB[STAGES];
#pragma unroll
    for (int s = 0; s < STAGES; s++) {
        dA0[s] = (unsigned)__cvta_generic_to_shared(&As[s][rowA0][cA * 4]);
        dA1[s] = (unsigned)__cvta_generic_to_shared(&As[s][rowA1][cA * 4]);
        dB[s]  = (unsigned)__cvta_generic_to_shared(&Bs[s][rowA0][cA * 4]);
    }

    float acc[2][4][4] = {};
    const int NK = D_MODEL / TKK;

    // prologue: stage 0
    cp16(dA0[0], srcA0, szA0);
    cp16(dA1[0], srcA1, szA1);
    cp16(dB[0],  srcB,  16);
    cp_commit();
    srcA0 += TKK; srcA1 += TKK; srcB += TKK;

    for (int k0 = 0; k0 < NK; k0++) {
        int s = k0 & 1;
        if (k0 + 1 < NK) {
            int sn = s ^ 1;
            cp16(dA0[sn], srcA0, szA0);
            cp16(dA1[sn], srcA1, szA1);
            cp16(dB[sn],  srcB,  16);
            cp_commit();
            srcA0 += TKK; srcA1 += TKK; srcB += TKK;
            cp_wait<1>();
        } else {
            cp_wait<0>();
        }
        __syncthreads();
#pragma unroll
        for (int k8 = 0; k8 < TKK; k8 += 8) {
            unsigned a[2][4], b[4][2];
#pragma unroll
            for (int mi = 0; mi < 2; mi++) {
                int rbase = wm + mi * 16 + g;
                a[mi][0] = f2tf(As[s][rbase][k8 + q]);
                a[mi][1] = f2tf(As[s][rbase + 8][k8 + q]);
                a[mi][2] = f2tf(As[s][rbase][k8 + q + 4]);
                a[mi][3] = f2tf(As[s][rbase + 8][k8 + q + 4]);
            }
#pragma unroll
            for (int ni = 0; ni < 4; ni++) {
                int cbase = wn + ni * 8 + g;
                b[ni][0] = f2tf(Bs[s][cbase][k8 + q]);
                b[ni][1] = f2tf(Bs[s][cbase][k8 + q + 4]);
            }
#pragma unroll
            for (int mi = 0; mi < 2; mi++)
#pragma unroll
                for (int ni = 0; ni < 4; ni++)
                    mma_tf32(acc[mi][ni], a[mi], b[ni]);
        }
        __syncthreads();
    }

    // epilogue: bias + exact gelu
#pragma unroll
    for (int mi = 0; mi < 2; mi++) {
#pragma unroll
        for (int half = 0; half < 2; half++) {
            int row = wm + mi * 16 + g + half * 8;
            int t = tok[row];
            if (t < 0) continue;
#pragma unroll
            for (int ni = 0; ni < 4; ni++) {
                int col = f0 + wn + ni * 8 + q * 2;
                float v0 = acc[mi][ni][half * 2 + 0] + b1[e * D_FF + col];
                float v1 = acc[mi][ni][half * 2 + 1] + b1[e * D_FF + col + 1];
                v0 = 0.5f * v0 * (1.0f + erff(v0 * 0.70710678118654752f));
                v1 = 0.5f * v1 * (1.0f + erff(v1 * 0.70710678118654752f));
                *(float2*)&g_H[(size_t)(r0 + row) * D_FF + col] = make_float2(v0, v1);
            }
        }
    }
}

// ======================================================================
// pass 2: out += gate * (H @ w2[e]^T + b2[e])
// grid is (n-tile, m-tile) so concurrent CTAs share the same H rows in L2
// ======================================================================
__global__ void __launch_bounds__(256) k_ffn2(const float* __restrict__ w2,
                                              const float* __restrict__ b2,
                                              float* __restrict__ out) {
    int e = g_tile_expert[blockIdx.y];
    if (e < 0) return;
    int r0 = blockIdx.y * TM;
    int c0 = blockIdx.x * TN;

    __shared__ float As[STAGES][TM][SK];
    __shared__ float Bs[STAGES][TN][SK];
    __shared__ int tok[TM];
    __shared__ float gate[TM];

    int tid = threadIdx.x;
    if (tid < TM) {
        tok[tid]  = g_sorted_token[r0 + tid];
        gate[tid] = g_sorted_gate[r0 + tid];
    }
    __syncthreads();
    if (tok[0] < 0) return;

    int lane = tid & 31, wid = tid >> 5;
    int wm = (wid & 3) * 32;
    int wn = (wid >> 2) * 32;
    int g = lane >> 2, q = lane & 3;

    int rowA0 = tid >> 2, cA = tid & 3;
    int rowA1 = rowA0 + 64;
    const float* ha = g_H + (size_t)r0 * D_FF;
    const float* srcA0 = ha + (size_t)rowA0 * D_FF + cA * 4;   // pad rows read zeros
    const float* srcA1 = ha + (size_t)rowA1 * D_FF + cA * 4;
    const float* wb = w2 + ((size_t)e * D_MODEL + c0) * D_FF;
    const float* srcB = wb + (size_t)rowA0 * D_FF + cA * 4;

    unsigned dA0[STAGES], dA1[STAGES], dB[STAGES];
#pragma unroll
    for (int s = 0; s < STAGES; s++) {
        dA0[s] = (unsigned)__cvta_generic_to_shared(&As[s][rowA0][cA * 4]);
        dA1[s] = (unsigned)__cvta_generic_to_shared(&As[s][rowA1][cA * 4]);
        dB[s]  = (unsigned)__cvta_generic_to_shared(&Bs[s][rowA0][cA * 4]);
    }

    float acc[2][4][4] = {};
    const int NK = D_FF / TKK;

    cp16(dA0[0], srcA0, 16);
    cp16(dA1[0], srcA1, 16);
    cp16(dB[0],  srcB,  16);
    cp_commit();
    srcA0 += TKK; srcA1 += TKK; srcB += TKK;

    for (int k0 = 0; k0 < NK; k0++) {
        int s = k0 & 1;
        if (k0 + 1 < NK) {
            int sn = s ^ 1;
            cp16(dA0[sn], srcA0, 16);
            cp16(dA1[sn], srcA1, 16);
            cp16(dB[sn],  srcB,  16);
            cp_commit();
            srcA0 += TKK; srcA1 += TKK; srcB += TKK;
            cp_wait<1>();
        } else {
            cp_wait<0>();
        }
        __syncthreads();
#pragma unroll
        for (int k8 = 0; k8 < TKK; k8 += 8) {
            unsigned a[2][4], b[4][2];
#pragma unroll
            for (int mi = 0; mi < 2; mi++) {
                int rbase = wm + mi * 16 + g;
                a[mi][0] = f2tf(As[s][rbase][k8 + q]);
                a[mi][1] = f2tf(As[s][rbase + 8][k8 + q]);
                a[mi][2] = f2tf(As[s][rbase][k8 + q + 4]);
                a[mi][3] = f2tf(As[s][rbase + 8][k8 + q + 4]);
            }
#pragma unroll
            for (int ni = 0; ni < 4; ni++) {
                int cbase = wn + ni * 8 + g;
                b[ni][0] = f2tf(Bs[s][cbase][k8 + q]);
                b[ni][1] = f2tf(Bs[s][cbase][k8 + q + 4]);
            }
#pragma unroll
            for (int mi = 0; mi < 2; mi++)
#pragma unroll
                for (int ni = 0; ni < 4; ni++)
                    mma_tf32(acc[mi][ni], a[mi], b[ni]);
        }
        __syncthreads();
    }

    // epilogue: gate * (acc + bias), 2 commutative atomicAdds per element
#pragma unroll
    for (int mi = 0; mi < 2; mi++) {
#pragma unroll
        for (int half = 0; half < 2; half++) {
            int row = wm + mi * 16 + g + half * 8;
            int t = tok[row];
            if (t < 0) continue;
            float gw = gate[row];
#pragma unroll
            for (int ni = 0; ni < 4; ni++) {
                int col = c0 + wn + ni * 8 + q * 2;
                float v0 = gw * (acc[mi][ni][half * 2 + 0] + b2[e * D_MODEL + col]);
                float v1 = gw * (acc[mi][ni][half * 2 + 1] + b2[e * D_MODEL + col + 1]);
                atomicAdd(&out[(size_t)t * D_MODEL + col], v0);
                atomicAdd(&out[(size_t)t * D_MODEL + col + 1], v1);
            }
        }
    }
}

// ---------------- launch ----------------
extern "C" void kernel_launch(void* const* d_in, const int* in_sizes, int n_in,
                              void* d_out, int out_size) {
    (void)in_sizes; (void)n_in; (void)out_size;
    const float* x  = (const float*)d_in[0];
    const float* rw = (const float*)d_in[1];
    const float* rb = (const float*)d_in[2];
    const float* w1 = (const float*)d_in[3];
    const float* b1 = (const float*)d_in[4];
    const float* w2 = (const float*)d_in[5];
    const float* b2 = (const float*)d_in[6];
    float* out = (float*)d_out;

    k_init<<<1024, 256>>>(out);
    k_router<<<T_TOKENS / 8, 256>>>(x, rw, rb);
    k_setup<<<1, 1>>>();
    k_scatter<<<(NPAIRS + 255) / 256, 256>>>();
    k_ffn1<<<dim3(MAX_TILES, D_FF / TN), 256>>>(x, w1, b1);
    k_ffn2<<<dim3(D_MODEL / TN, MAX_TILES), 256>>>(w2, b2, out);
}

// round 12
// speedup vs baseline: 7.4924x; 1.3164x over previous
#include <cuda_runtime.h>
#include <math.h>

#define D_MODEL  1024
#define D_FF     4096
#define N_EXPERTS 8
#define T_TOKENS 8192
#define TOPK     2
#define NPAIRS   (T_TOKENS * TOPK)          // 16384

#define BM  128                              // CTA tile M
#define BN  128                              // CTA tile N
#define TKK 16
#define SK  (TKK + 4)                        // smem row stride (words) -> conflict-free frag reads
#define STAGES 2
#define ROWS_CAP  (NPAIRS + N_EXPERTS * BM) // 17408
#define MAX_TILES (ROWS_CAP / BM)           // 136

// ---------------- static device scratch (allocation-free) ----------------
__device__ float g_H[(size_t)ROWS_CAP * D_FF];   // gelu(x@w1^T); pad rows stay 0
__device__ int   g_sorted_token[ROWS_CAP];
__device__ float g_sorted_gate[ROWS_CAP];
__device__ int   g_off[N_EXPERTS + 1];
__device__ int   g_count[N_EXPERTS];
__device__ int   g_tile_expert[MAX_TILES];
__device__ int   g_pair_expert[NPAIRS];
__device__ float g_pair_gate[NPAIRS];
__device__ int   g_pair_rank[NPAIRS];

// ---------------- helpers ----------------
__device__ __forceinline__ unsigned f2tf(float f) {
    unsigned u;
    asm("cvt.rna.tf32.f32 %0, %1;" : "=r"(u) : "f"(f));
    return u;
}

__device__ __forceinline__ void mma_tf32(float* c, const unsigned* a, const unsigned* b) {
    asm volatile(
        "mma.sync.aligned.m16n8k8.row.col.f32.tf32.tf32.f32 "
        "{%0,%1,%2,%3}, {%4,%5,%6,%7}, {%8,%9}, {%0,%1,%2,%3};"
        : "+f"(c[0]), "+f"(c[1]), "+f"(c[2]), "+f"(c[3])
        : "r"(a[0]), "r"(a[1]), "r"(a[2]), "r"(a[3]), "r"(b[0]), "r"(b[1]));
}

__device__ __forceinline__ void cp16(unsigned dst, const void* src, int src_bytes) {
    asm volatile("cp.async.cg.shared.global [%0], [%1], 16, %2;"
                 :: "r"(dst), "l"(src), "r"(src_bytes));
}
__device__ __forceinline__ void cp_commit() {
    asm volatile("cp.async.commit_group;");
}
template <int N>
__device__ __forceinline__ void cp_wait() {
    asm volatile("cp.async.wait_group %0;" :: "n"(N));
}

// ---------------- init ----------------
__global__ void k_init(float* __restrict__ out) {
    int stride = gridDim.x * blockDim.x;
    int i0 = blockIdx.x * blockDim.x + threadIdx.x;
    const int n = T_TOKENS * D_MODEL;
    for (int i = i0; i < n; i += stride) out[i] = 0.0f;
    for (int i = i0; i < ROWS_CAP; i += stride) g_sorted_token[i] = -1;
    if (i0 < N_EXPERTS) g_count[i0] = 0;
}

// ---------------- router: one warp per token ----------------
__global__ void k_router(const float* __restrict__ x,
                         const float* __restrict__ rw,
                         const float* __restrict__ rb) {
    int warp = (blockIdx.x * blockDim.x + threadIdx.x) >> 5;
    int lane = threadIdx.x & 31;
    if (warp >= T_TOKENS) return;
    const float* xt = x + (size_t)warp * D_MODEL;

    float lg[N_EXPERTS];
#pragma unroll
    for (int e = 0; e < N_EXPERTS; e++) {
        const float* we = rw + e * D_MODEL;
        float s = 0.0f;
        for (int d = lane; d < D_MODEL; d += 32) s = fmaf(xt[d], we[d], s);
#pragma unroll
        for (int o = 16; o > 0; o >>= 1) s += __shfl_down_sync(0xffffffffu, s, o);
        lg[e] = s;
    }
    if (lane == 0) {
        float m = -1e30f;
#pragma unroll
        for (int e = 0; e < N_EXPERTS; e++) { lg[e] += rb[e]; m = fmaxf(m, lg[e]); }
        float p[N_EXPERTS];
#pragma unroll
        for (int e = 0; e < N_EXPERTS; e++) p[e] = expf(lg[e] - m);
        int i1 = 0;
#pragma unroll
        for (int e = 1; e < N_EXPERTS; e++) if (p[e] > p[i1]) i1 = e;
        int i2 = (i1 == 0) ? 1 : 0;
#pragma unroll
        for (int e = 0; e < N_EXPERTS; e++) if (e != i1 && p[e] > p[i2]) i2 = e;
        float s2 = p[i1] + p[i2];
        g_pair_expert[warp * 2 + 0] = i1;
        g_pair_expert[warp * 2 + 1] = i2;
        g_pair_gate[warp * 2 + 0] = p[i1] / s2;
        g_pair_gate[warp * 2 + 1] = p[i2] / s2;
        g_pair_rank[warp * 2 + 0] = atomicAdd(&g_count[i1], 1);
        g_pair_rank[warp * 2 + 1] = atomicAdd(&g_count[i2], 1);
    }
}

// ---------------- offsets + tile->expert map ----------------
__global__ void k_setup() {
    int off = 0;
    for (int e = 0; e < N_EXPERTS; e++) {
        g_off[e] = off;
        off += (g_count[e] + BM - 1) / BM * BM;
    }
    g_off[N_EXPERTS] = off;
    int nt = off / BM;
    for (int i = 0; i < MAX_TILES; i++) {
        int te = -1;
        if (i < nt) {
            int r = i * BM;
            for (int e = 0; e < N_EXPERTS; e++)
                if (r >= g_off[e] && r < g_off[e + 1]) { te = e; break; }
        }
        g_tile_expert[i] = te;
    }
}

// ---------------- scatter ----------------
__global__ void k_scatter() {
    int i = blockIdx.x * blockDim.x + threadIdx.x;
    if (i >= NPAIRS) return;
    int e = g_pair_expert[i];
    int r = g_off[e] + g_pair_rank[i];
    g_sorted_token[r] = i >> 1;
    g_sorted_gate[r]  = g_pair_gate[i];
}

// ======================================================================
// pass 1: H = gelu(X_e @ w1[e]^T + b1[e])
// CTA tile 128x128x16, warp tile 64x32 (2Mx4N warps), tf32 mma.sync,
// cp.async double-buffered.
// ======================================================================
__global__ void __launch_bounds__(256) k_ffn1(const float* __restrict__ x,
                                              const float* __restrict__ w1,
                                              const float* __restrict__ b1) {
    int e = g_tile_expert[blockIdx.x];
    if (e < 0) return;
    int r0 = blockIdx.x * BM;
    int f0 = blockIdx.y * BN;

    __shared__ float As[STAGES][BM][SK];
    __shared__ float Bs[STAGES][BN][SK];
    __shared__ int tok[BM];

    int tid = threadIdx.x;
    if (tid < BM) tok[tid] = g_sorted_token[r0 + tid];
    __syncthreads();
    if (tok[0] < 0) return;

    int lane = tid & 31, wid = tid >> 5;
    int wm = (wid & 1) * 64;          // warp M offset (0 or 64)
    int wn = (wid >> 1) * 32;         // warp N offset (0..96)
    int g = lane >> 2, q = lane & 3;

    // per-thread cp.async slots (k-invariant): 512 float4 per matrix / 256 thr = 2 each
    int row0 = tid >> 2, cA = tid & 3;
    int row1 = row0 + 64;
    int t0 = tok[row0], t1 = tok[row1];
    const float* srcA0 = x + (t0 >= 0 ? (size_t)t0 * D_MODEL : 0) + cA * 4;
    const float* srcA1 = x + (t1 >= 0 ? (size_t)t1 * D_MODEL : 0) + cA * 4;
    int szA0 = t0 >= 0 ? 16 : 0, szA1 = t1 >= 0 ? 16 : 0;
    const float* wb = w1 + ((size_t)e * D_FF + f0) * D_MODEL;
    const float* srcB0 = wb + (size_t)row0 * D_MODEL + cA * 4;
    const float* srcB1 = wb + (size_t)row1 * D_MODEL + cA * 4;

    unsigned dA0[STAGES], dA1[STAGES], dB0[STAGES], dB1[STAGES];
#pragma unroll
    for (int s = 0; s < STAGES; s++) {
        dA0[s] = (unsigned)__cvta_generic_to_shared(&As[s][row0][cA * 4]);
        dA1[s] = (unsigned)__cvta_generic_to_shared(&As[s][row1][cA * 4]);
        dB0[s] = (unsigned)__cvta_generic_to_shared(&Bs[s][row0][cA * 4]);
        dB1[s] = (unsigned)__cvta_generic_to_shared(&Bs[s][row1][cA * 4]);
    }

    float acc[4][4][4] = {};
    const int NK = D_MODEL / TKK;

    cp16(dA0[0], srcA0, szA0);
    cp16(dA1[0], srcA1, szA1);
    cp16(dB0[0], srcB0, 16);
    cp16(dB1[0], srcB1, 16);
    cp_commit();
    srcA0 += TKK; srcA1 += TKK; srcB0 += TKK; srcB1 += TKK;

    for (int k0 = 0; k0 < NK; k0++) {
        int s = k0 & 1;
        if (k0 + 1 < NK) {
            int sn = s ^ 1;
            cp16(dA0[sn], srcA0, szA0);
            cp16(dA1[sn], srcA1, szA1);
            cp16(dB0[sn], srcB0, 16);
            cp16(dB1[sn], srcB1, 16);
            cp_commit();
            srcA0 += TKK; srcA1 += TKK; srcB0 += TKK; srcB1 += TKK;
            cp_wait<1>();
        } else {
            cp_wait<0>();
        }
        __syncthreads();
#pragma unroll
        for (int k8 = 0; k8 < TKK; k8 += 8) {
            unsigned a[4][4], b[4][2];
#pragma unroll
            for (int mi = 0; mi < 4; mi++) {
                int rbase = wm + mi * 16 + g;
                a[mi][0] = f2tf(As[s][rbase][k8 + q]);
                a[mi][1] = f2tf(As[s][rbase + 8][k8 + q]);
                a[mi][2] = f2tf(As[s][rbase][k8 + q + 4]);
                a[mi][3] = f2tf(As[s][rbase + 8][k8 + q + 4]);
            }
#pragma unroll
            for (int ni = 0; ni < 4; ni++) {
                int cbase = wn + ni * 8 + g;
                b[ni][0] = f2tf(Bs[s][cbase][k8 + q]);
                b[ni][1] = f2tf(Bs[s][cbase][k8 + q + 4]);
            }
#pragma unroll
            for (int mi = 0; mi < 4; mi++)
#pragma unroll
                for (int ni = 0; ni < 4; ni++)
                    mma_tf32(acc[mi][ni], a[mi], b[ni]);
        }
        __syncthreads();
    }

    // epilogue: bias + exact gelu
#pragma unroll
    for (int mi = 0; mi < 4; mi++) {
#pragma unroll
        for (int half = 0; half < 2; half++) {
            int row = wm + mi * 16 + g + half * 8;
            int t = tok[row];
            if (t < 0) continue;
#pragma unroll
            for (int ni = 0; ni < 4; ni++) {
                int col = f0 + wn + ni * 8 + q * 2;
                float v0 = acc[mi][ni][half * 2 + 0] + b1[e * D_FF + col];
                float v1 = acc[mi][ni][half * 2 + 1] + b1[e * D_FF + col + 1];
                v0 = 0.5f * v0 * (1.0f + erff(v0 * 0.70710678118654752f));
                v1 = 0.5f * v1 * (1.0f + erff(v1 * 0.70710678118654752f));
                *(float2*)&g_H[(size_t)(r0 + row) * D_FF + col] = make_float2(v0, v1);
            }
        }
    }
}

// ======================================================================
// pass 2: out += gate * (H @ w2[e]^T + b2[e])
// grid (n-tile, m-tile) so concurrent CTAs share H rows in L2.
// ======================================================================
__global__ void __launch_bounds__(256) k_ffn2(const float* __restrict__ w2,
                                              const float* __restrict__ b2,
                                              float* __restrict__ out) {
    int e = g_tile_expert[blockIdx.y];
    if (e < 0) return;
    int r0 = blockIdx.y * BM;
    int c0 = blockIdx.x * BN;

    __shared__ float As[STAGES][BM][SK];
    __shared__ float Bs[STAGES][BN][SK];
    __shared__ int tok[BM];
    __shared__ float gate[BM];

    int tid = threadIdx.x;
    if (tid < BM) {
        tok[tid]  = g_sorted_token[r0 + tid];
        gate[tid] = g_sorted_gate[r0 + tid];
    }
    __syncthreads();
    if (tok[0] < 0) return;

    int lane = tid & 31, wid = tid >> 5;
    int wm = (wid & 1) * 64;
    int wn = (wid >> 1) * 32;
    int g = lane >> 2, q = lane & 3;

    int row0 = tid >> 2, cA = tid & 3;
    int row1 = row0 + 64;
    const float* ha = g_H + (size_t)r0 * D_FF;
    const float* srcA0 = ha + (size_t)row0 * D_FF + cA * 4;   // pad rows read zeros
    const float* srcA1 = ha + (size_t)row1 * D_FF + cA * 4;
    const float* wb = w2 + ((size_t)e * D_MODEL + c0) * D_FF;
    const float* srcB0 = wb + (size_t)row0 * D_FF + cA * 4;
    const float* srcB1 = wb + (size_t)row1 * D_FF + cA * 4;

    unsigned dA0[STAGES], dA1[STAGES], dB0[STAGES], dB1[STAGES];
#pragma unroll
    for (int s = 0; s < STAGES; s++) {
        dA0[s] = (unsigned)__cvta_generic_to_shared(&As[s][row0][cA * 4]);
        dA1[s] = (unsigned)__cvta_generic_to_shared(&As[s][row1][cA * 4]);
        dB0[s] = (unsigned)__cvta_generic_to_shared(&Bs[s][row0][cA * 4]);
        dB1[s] = (unsigned)__cvta_generic_to_shared(&Bs[s][row1][cA * 4]);
    }

    float acc[4][4][4] = {};
    const int NK = D_FF / TKK;

    cp16(dA0[0], srcA0, 16);
    cp16(dA1[0], srcA1, 16);
    cp16(dB0[0], srcB0, 16);
    cp16(dB1[0], srcB1, 16);
    cp_commit();
    srcA0 += TKK; srcA1 += TKK; srcB0 += TKK; srcB1 += TKK;

    for (int k0 = 0; k0 < NK; k0++) {
        int s = k0 & 1;
        if (k0 + 1 < NK) {
            int sn = s ^ 1;
            cp16(dA0[sn], srcA0, 16);
            cp16(dA1[sn], srcA1, 16);
            cp16(dB0[sn], srcB0, 16);
            cp16(dB1[sn], srcB1, 16);
            cp_commit();
            srcA0 += TKK; srcA1 += TKK; srcB0 += TKK; srcB1 += TKK;
            cp_wait<1>();
        } else {
            cp_wait<0>();
        }
        __syncthreads();
#pragma unroll
        for (int k8 = 0; k8 < TKK; k8 += 8) {
            unsigned a[4][4], b[4][2];
#pragma unroll
            for (int mi = 0; mi < 4; mi++) {
                int rbase = wm + mi * 16 + g;
                a[mi][0] = f2tf(As[s][rbase][k8 + q]);
                a[mi][1] = f2tf(As[s][rbase + 8][k8 + q]);
                a[mi][2] = f2tf(As[s][rbase][k8 + q + 4]);
                a[mi][3] = f2tf(As[s][rbase + 8][k8 + q + 4]);
            }
#pragma unroll
            for (int ni = 0; ni < 4; ni++) {
                int cbase = wn + ni * 8 + g;
                b[ni][0] = f2tf(Bs[s][cbase][k8 + q]);
                b[ni][1] = f2tf(Bs[s][cbase][k8 + q + 4]);
            }
#pragma unroll
            for (int mi = 0; mi < 4; mi++)
#pragma unroll
                for (int ni = 0; ni < 4; ni++)
                    mma_tf32(acc[mi][ni], a[mi], b[ni]);
        }
        __syncthreads();
    }

    // epilogue: gate * (acc + bias), 2 commutative atomicAdds per output elem
#pragma unroll
    for (int mi = 0; mi < 4; mi++) {
#pragma unroll
        for (int half = 0; half < 2; half++) {
            int row = wm + mi * 16 + g + half * 8;
            int t = tok[row];
            if (t < 0) continue;
            float gw = gate[row];
#pragma unroll
            for (int ni = 0; ni < 4; ni++) {
                int col = c0 + wn + ni * 8 + q * 2;
                float v0 = gw * (acc[mi][ni][half * 2 + 0] + b2[e * D_MODEL + col]);
                float v1 = gw * (acc[mi][ni][half * 2 + 1] + b2[e * D_MODEL + col + 1]);
                atomicAdd(&out[(size_t)t * D_MODEL + col], v0);
                atomicAdd(&out[(size_t)t * D_MODEL + col + 1], v1);
            }
        }
    }
}

// ---------------- launch ----------------
extern "C" void kernel_launch(void* const* d_in, const int* in_sizes, int n_in,
                              void* d_out, int out_size) {
    (void)in_sizes; (void)n_in; (void)out_size;
    const float* x  = (const float*)d_in[0];
    const float* rw = (const float*)d_in[1];
    const float* rb = (const float*)d_in[2];
    const float* w1 = (const float*)d_in[3];
    const float* b1 = (const float*)d_in[4];
    const float* w2 = (const float*)d_in[5];
    const float* b2 = (const float*)d_in[6];
    float* out = (float*)d_out;

    k_init<<<1024, 256>>>(out);
    k_router<<<T_TOKENS / 8, 256>>>(x, rw, rb);
    k_setup<<<1, 1>>>();
    k_scatter<<<(NPAIRS + 255) / 256, 256>>>();
    k_ffn1<<<dim3(MAX_TILES, D_FF / BN), 256>>>(x, w1, b1);
    k_ffn2<<<dim3(D_MODEL / BN, MAX_TILES), 256>>>(w2, b2, out);
}